// round 1
// baseline (speedup 1.0000x reference)
#include <cuda_runtime.h>
#include <cuda_fp16.h>
#include <cstdint>

// ---------------- problem constants ----------------
#define L_TOT  9291      // latent size
#define LP     9344      // padded to 146*64
#define NBATCH 16
#define NSTEPS 256
#define BM     64        // rows per CTA
#define BK     64        // k per pipeline stage
#define NI     73        // k-iterations per K-half (2*73*64 = 9344)
#define STAGES 4
#define SCALE      16384.0f
#define INV_SCALE  (1.0f/16384.0f)

// ---------------- device scratch (no runtime allocation allowed) ----------------
__device__ __align__(16) __half d_E[(size_t)LP * LP];        // scaled (A - I), fp16, padded
__device__ __align__(16) float  d_Th[2][LP * NBATCH];        // fp32 master state, ping-pong
__device__ __align__(16) __half d_Thh[2][LP * NBATCH];       // fp16 shadow state for MMA
__device__ __align__(16) float  d_bvec[LP];                  // Bm column, padded

// ---------------- small PTX helpers ----------------
__device__ __forceinline__ void cp_async16(uint32_t saddr, const void* gaddr) {
    asm volatile("cp.async.cg.shared.global [%0], [%1], 16;" :: "r"(saddr), "l"(gaddr));
}
__device__ __forceinline__ void cp_commit() { asm volatile("cp.async.commit_group;"); }

__device__ __forceinline__ void ldmatrix_x4(uint32_t& r0, uint32_t& r1, uint32_t& r2, uint32_t& r3, uint32_t addr) {
    asm volatile("ldmatrix.sync.aligned.m8n8.x4.shared.b16 {%0,%1,%2,%3}, [%4];"
                 : "=r"(r0), "=r"(r1), "=r"(r2), "=r"(r3) : "r"(addr));
}
__device__ __forceinline__ void ldmatrix_x2_trans(uint32_t& r0, uint32_t& r1, uint32_t addr) {
    asm volatile("ldmatrix.sync.aligned.m8n8.x2.trans.shared.b16 {%0,%1}, [%2];"
                 : "=r"(r0), "=r"(r1) : "r"(addr));
}
__device__ __forceinline__ void mma16816(float* c, uint32_t a0, uint32_t a1, uint32_t a2, uint32_t a3,
                                         uint32_t b0, uint32_t b1) {
    asm volatile("mma.sync.aligned.m16n8k16.row.col.f32.f16.f16.f32 "
                 "{%0,%1,%2,%3}, {%4,%5,%6,%7}, {%8,%9}, {%0,%1,%2,%3};"
                 : "+f"(c[0]), "+f"(c[1]), "+f"(c[2]), "+f"(c[3])
                 : "r"(a0), "r"(a1), "r"(a2), "r"(a3), "r"(b0), "r"(b1));
}

// ---------------- kernel 1: A (fp32) -> E = (A - I)*SCALE (fp16, padded) ----------------
__global__ void __launch_bounds__(256) conv_kernel(const float* __restrict__ A) {
    size_t idx = ((size_t)blockIdx.x * 256 + threadIdx.x) * 4;   // 4 halves per thread
    int i = (int)(idx / LP);
    int j = (int)(idx % LP);
    float v[4];
#pragma unroll
    for (int u = 0; u < 4; u++) {
        int jj = j + u;
        float x = 0.f;
        if (i < L_TOT && jj < L_TOT) {
            x = A[(size_t)i * L_TOT + jj];
            if (i == jj) x -= 1.0f;
        }
        v[u] = x * SCALE;
    }
    __half2* p = reinterpret_cast<__half2*>(d_E + idx);
    p[0] = __floats2half2_rn(v[0], v[1]);
    p[1] = __floats2half2_rn(v[2], v[3]);
}

// ---------------- kernel 2: init state + b vector ----------------
__global__ void __launch_bounds__(256) init_kernel(const float* __restrict__ Bm,
                                                   const float* __restrict__ theta) {
    int idx = blockIdx.x * 256 + threadIdx.x;
    if (idx < LP * NBATCH) {
        int k = idx >> 4;
        float v = (k < L_TOT) ? theta[k] : 0.f;
        d_Th[0][idx]  = v;
        d_Thh[0][idx] = __float2half(v);
        if ((idx & 15) == 0) d_bvec[k] = (k < L_TOT) ? Bm[k] : 0.f;
    }
}

// ---------------- kernel 3: one recurrence step ----------------
// Theta' = Theta + (E_s @ Theta_h) * INV_SCALE + bvec * x[:, t]
// Grid: 146 CTAs x 256 threads. Warps 0-3: K-half 0, warps 4-7: K-half 1, mt = wid&3.
__global__ void __launch_bounds__(256) step_kernel(const float* __restrict__ xs, int t, int parity) {
    extern __shared__ char smem[];
    // layout: sA [2 halves][STAGES][64*64] halves  = 65536 B
    //         sB [2 halves][STAGES][64*24] halves  = 24576 B (stride 24 kills ldmatrix conflicts)
    //         sD [64][17] float                    =  4352 B
    float* sD = (float*)(smem + 90112);
    const uint32_t smem_u = (uint32_t)__cvta_generic_to_shared(smem);

    const int tid = threadIdx.x;
    const int wid = tid >> 5, lane = tid & 31;
    const int row0 = blockIdx.x * BM;

    const float*  __restrict__ Th_src  = d_Th[parity];
    float*        __restrict__ Th_dst  = d_Th[parity ^ 1];
    const __half* __restrict__ Thh_src = d_Thh[parity];
    __half*       __restrict__ Thh_dst = d_Thh[parity ^ 1];

    // ---- loader address precompute (4 A-chunks + 1 B-chunk per thread per iter) ----
    uint32_t a_s[4];
    const __half* a_g[4];
#pragma unroll
    for (int u = 0; u < 4; u++) {
        int qa = tid + 256 * u;               // 0..1023, two 512-chunk A tiles
        int hh = qa >> 9, q = qa & 511;
        int r = q >> 3, c = q & 7;
        int cs = c ^ (r & 7);                 // XOR swizzle for conflict-free ldmatrix
        a_g[u] = d_E + (size_t)(row0 + r) * LP + (size_t)hh * (NI * BK) + c * 8;
        a_s[u] = smem_u + (uint32_t)(hh * (STAGES * 4096) + r * 64 + cs * 8) * 2;
    }
    const int hhB = tid >> 7, qB = tid & 127, rB = qB >> 1, cB = qB & 1;
    const __half* b_g = Thh_src + ((size_t)hhB * (NI * BK) + rB) * 16 + cB * 8;
    const uint32_t b_s = smem_u + 65536 + (uint32_t)(hhB * (STAGES * 1536) + rB * 24 + cB * 8) * 2;

    // ---- compute-side precompute ----
    const int h  = wid >> 2;        // K-half
    const int mt = wid & 3;         // m-tile (16 rows)
    const uint32_t aTile = smem_u + (uint32_t)(h * (STAGES * 4096)) * 2;
    const uint32_t bTile = smem_u + 65536 + (uint32_t)(h * (STAGES * 1536)) * 2;
    const int ar  = mt * 16 + (lane & 15);
    const int ach = lane >> 4;
    const int brow = lane & 15;

    float acc[2][4];
#pragma unroll
    for (int n = 0; n < 2; n++)
#pragma unroll
        for (int k = 0; k < 4; k++) acc[n][k] = 0.f;

    auto load_tiles = [&](int i, int s) {
        size_t kadd = (size_t)i * BK;
#pragma unroll
        for (int u = 0; u < 4; u++)
            cp_async16(a_s[u] + s * 8192, a_g[u] + kadd);
        cp_async16(b_s + s * 3072, b_g + kadd * 16);
    };

    // prologue: fill STAGES-1 stages
#pragma unroll
    for (int s = 0; s < STAGES - 1; s++) { load_tiles(s, s); cp_commit(); }

    for (int i = 0; i < NI; i++) {
        const int li = i + STAGES - 1;
        if (li < NI) load_tiles(li, li & 3);
        cp_commit();
        asm volatile("cp.async.wait_group %0;" :: "n"(STAGES - 1));
        __syncthreads();

        const int s = i & 3;
        const uint32_t aBase = aTile + s * 8192;
        const uint32_t bBase = bTile + s * 3072;
#pragma unroll
        for (int kk = 0; kk < 4; kk++) {
            const int c  = kk * 2 + ach;
            const int cs = c ^ (ar & 7);
            uint32_t a0, a1, a2, a3;
            ldmatrix_x4(a0, a1, a2, a3, aBase + (uint32_t)(ar * 64 + cs * 8) * 2);
            const uint32_t bAddr = bBase + (uint32_t)((kk * 16 + brow) * 24) * 2;
            uint32_t b00, b01, b10, b11;
            ldmatrix_x2_trans(b00, b01, bAddr);        // n cols 0-7
            ldmatrix_x2_trans(b10, b11, bAddr + 16);   // n cols 8-15
            mma16816(acc[0], a0, a1, a2, a3, b00, b01);
            mma16816(acc[1], a0, a1, a2, a3, b10, b11);
        }
        __syncthreads();
    }

    // ---- reduce the two K-halves through shared memory ----
    const int dr = mt * 16 + (lane >> 2);
    const int dc = (lane & 3) * 2;
    if (h == 0) {
#pragma unroll
        for (int n = 0; n < 2; n++) {
            sD[dr * 17 + n * 8 + dc]           = acc[n][0];
            sD[dr * 17 + n * 8 + dc + 1]       = acc[n][1];
            sD[(dr + 8) * 17 + n * 8 + dc]     = acc[n][2];
            sD[(dr + 8) * 17 + n * 8 + dc + 1] = acc[n][3];
        }
    }
    __syncthreads();
    if (h == 1) {
#pragma unroll
        for (int n = 0; n < 2; n++) {
            sD[dr * 17 + n * 8 + dc]           += acc[n][0];
            sD[dr * 17 + n * 8 + dc + 1]       += acc[n][1];
            sD[(dr + 8) * 17 + n * 8 + dc]     += acc[n][2];
            sD[(dr + 8) * 17 + n * 8 + dc + 1] += acc[n][3];
        }
    }
    __syncthreads();

    // ---- state update: fp32 master + fp16 shadow ----
#pragma unroll
    for (int e = 0; e < 4; e++) {
        int idx = tid + 256 * e;                 // 1024 = 64 rows * 16 batch
        int r = idx >> 4, b = idx & 15;
        int grow = row0 + r;
        float val = Th_src[grow * 16 + b]
                  + sD[r * 17 + b] * INV_SCALE
                  + d_bvec[grow] * xs[b * NSTEPS + t];
        Th_dst[grow * 16 + b]  = val;
        Thh_dst[grow * 16 + b] = __float2half(val);
    }
}

// ---------------- kernel 4: MLP epilogue ----------------
// grid (16 batches, 16 t-tiles of 16), 256 threads = 4 groups of 64 (one t each per pass)
__global__ void __launch_bounds__(256) mlp_kernel(float* __restrict__ out) {
    __shared__ float sW1r[64], sb1r[64], sW2r[64 * 64], sb2r[64], sW3r[64], sb3r[1];
    __shared__ float sW1c[64], sb1c[64], sW2c[64 * 64], sb2c[64], sW3c[64 * 10], sb3c[10];
    __shared__ float sh1[4][64];
    __shared__ float sred[4][2][10];

    const int b  = blockIdx.x;
    const int t0 = blockIdx.y * 16;
    const float* __restrict__ Th = d_Th[0];   // final state after 256 steps

    // gather + unflatten this batch's parameters (W2 / class-W3 stored transposed)
    for (int k = threadIdx.x; k < L_TOT; k += 256) {
        float v = Th[k * 16 + b];
        if      (k < 64)   sW1r[k] = v;
        else if (k < 128)  sb1r[k - 64] = v;
        else if (k < 4224) { int o = (k - 128) >> 6, in = (k - 128) & 63; sW2r[in * 64 + o] = v; }
        else if (k < 4288) sb2r[k - 4224] = v;
        else if (k < 4352) sW3r[k - 4288] = v;
        else if (k < 4353) sb3r[0] = v;
        else if (k < 4417) sW1c[k - 4353] = v;
        else if (k < 4481) sb1c[k - 4417] = v;
        else if (k < 8577) { int o = (k - 4481) >> 6, in = (k - 4481) & 63; sW2c[in * 64 + o] = v; }
        else if (k < 8641) sb2c[k - 8577] = v;
        else if (k < 9281) { int o = (k - 8641) >> 6, in = (k - 8641) & 63; sW3c[in * 10 + o] = v; }
        else               sb3c[k - 9281] = v;
    }
    __syncthreads();

    const int g = threadIdx.x >> 6, i = threadIdx.x & 63;
    const int wing = (threadIdx.x >> 5) & 1, lane = threadIdx.x & 31;

    for (int tl = 0; tl < 4; tl++) {
        const int t = t0 + tl * 4 + g;
        const float ts = (float)t * (1.0f / 255.0f);

        // ---- reconstruction branch ----
        float h1 = fmaxf(fmaf(sW1r[i], ts, sb1r[i]), 0.f);
        sh1[g][i] = h1;
        __syncthreads();
        float a2 = sb2r[i];
#pragma unroll
        for (int j = 0; j < 64; j++) a2 = fmaf(sW2r[j * 64 + i], sh1[g][j], a2);
        float h2 = fmaxf(a2, 0.f);
        float v = sW3r[i] * h2;
#pragma unroll
        for (int off = 16; off > 0; off >>= 1) v += __shfl_down_sync(0xffffffffu, v, off);
        if (lane == 0) sred[g][wing][0] = v;
        __syncthreads();
        if (i == 0) out[b * 256 + t] = sred[g][0][0] + sred[g][1][0] + sb3r[0];
        __syncthreads();

        // ---- classification branch ----
        float h1c = fmaxf(fmaf(sW1c[i], ts, sb1c[i]), 0.f);
        sh1[g][i] = h1c;
        __syncthreads();
        float a2c = sb2c[i];
#pragma unroll
        for (int j = 0; j < 64; j++) a2c = fmaf(sW2c[j * 64 + i], sh1[g][j], a2c);
        float h2c = fmaxf(a2c, 0.f);
        float vo[10];
#pragma unroll
        for (int o = 0; o < 10; o++) vo[o] = sW3c[i * 10 + o] * h2c;
#pragma unroll
        for (int off = 16; off > 0; off >>= 1)
#pragma unroll
            for (int o = 0; o < 10; o++) vo[o] += __shfl_down_sync(0xffffffffu, vo[o], off);
        if (lane == 0)
#pragma unroll
            for (int o = 0; o < 10; o++) sred[g][wing][o] = vo[o];
        __syncthreads();
        if (i < 10) out[4096 + (b * 256 + t) * 10 + i] = sred[g][0][i] + sred[g][1][i] + sb3c[i];
        __syncthreads();
    }
}

// ---------------- host launch ----------------
extern "C" void kernel_launch(void* const* d_in, const int* in_sizes, int n_in,
                              void* d_out, int out_size) {
    const float* xs    = (const float*)d_in[0];   // (16, 256, 1)
    const float* A     = (const float*)d_in[1];   // (9291, 9291)
    const float* Bm    = (const float*)d_in[2];   // (9291, 1)
    const float* theta = (const float*)d_in[3];   // (9291,)
    float* out = (float*)d_out;                   // 4096 recon + 40960 class fp32

    constexpr int SMEM_BYTES = 65536 + 24576 + 64 * 17 * 4;   // 94464
    cudaFuncSetAttribute(step_kernel, cudaFuncAttributeMaxDynamicSharedMemorySize, SMEM_BYTES);

    // E = (A - I) * 2^14 in fp16, zero-padded to 9344x9344
    conv_kernel<<<(int)(((size_t)LP * LP / 4 + 255) / 256), 256>>>(A);
    // initial state
    init_kernel<<<(LP * NBATCH + 255) / 256, 256>>>(Bm, theta);
    // 256 sequential recurrence steps (graph-captured launches; ping-pong buffers)
    for (int t = 0; t < NSTEPS; t++)
        step_kernel<<<LP / BM, 256, SMEM_BYTES>>>(xs, t, t & 1);
    // MLP readout
    mlp_kernel<<<dim3(16, 16), 256>>>(out);
}

// round 2
// speedup vs baseline: 1.2331x; 1.2331x over previous
#include <cuda_runtime.h>
#include <cuda_fp16.h>
#include <cstdint>

// ---------------- problem constants ----------------
#define L_TOT  9291
#define LP     9344          // 146*64
#define NT     146           // 64-wide tiles per dimension
#define NI     73            // k-iterations per K-half
#define NSTEPS 256
#define STAGES 8
#define STAGE_BYTES 20480    // 2x8KB A + 2x2KB B
#define SCALE      16384.0f
#define INV_SCALE  (1.0f/16384.0f)

// ---------------- device scratch ----------------
__device__ __align__(16) __half d_Er[(size_t)NT * NT * 4096];  // repacked scaled (A-I), fp16, swizzled tiles
__device__ __align__(16) float  d_Th[2][LP * 16];              // fp32 master state, ping-pong
__device__ __align__(16) __half d_Thh[2][NT * 1024];           // fp16 shadow state, swizzled [n][k] tiles
__device__ __align__(16) float  d_bvec[LP];

// ---------------- PTX helpers ----------------
__device__ __forceinline__ void mbar_init(uint32_t a, uint32_t cnt) {
    asm volatile("mbarrier.init.shared.b64 [%0], %1;" :: "r"(a), "r"(cnt) : "memory");
}
__device__ __forceinline__ void mbar_arrive(uint32_t a) {
    asm volatile("mbarrier.arrive.shared.b64 _, [%0];" :: "r"(a) : "memory");
}
__device__ __forceinline__ void mbar_expect_tx(uint32_t a, uint32_t bytes) {
    asm volatile("mbarrier.arrive.expect_tx.shared.b64 _, [%0], %1;" :: "r"(a), "r"(bytes) : "memory");
}
__device__ __forceinline__ void mbar_wait(uint32_t a, uint32_t parity) {
    asm volatile(
        "{\n\t.reg .pred P;\n"
        "W%=:\n\tmbarrier.try_wait.parity.acquire.cta.shared::cta.b64 P, [%0], %1, 0x989680;\n"
        "\t@P bra D%=;\n\tbra W%=;\nD%=:\n\t}"
        :: "r"(a), "r"(parity) : "memory");
}
__device__ __forceinline__ void bulk_ld(uint32_t dst, const void* src, uint32_t bytes, uint32_t mb) {
    asm volatile("cp.async.bulk.shared::cluster.global.mbarrier::complete_tx::bytes [%0], [%1], %2, [%3];"
                 :: "r"(dst), "l"(src), "r"(bytes), "r"(mb) : "memory");
}
__device__ __forceinline__ void ldmatrix_x4(uint32_t& r0, uint32_t& r1, uint32_t& r2, uint32_t& r3, uint32_t addr) {
    asm volatile("ldmatrix.sync.aligned.m8n8.x4.shared.b16 {%0,%1,%2,%3}, [%4];"
                 : "=r"(r0), "=r"(r1), "=r"(r2), "=r"(r3) : "r"(addr));
}
__device__ __forceinline__ void ldmatrix_x2(uint32_t& r0, uint32_t& r1, uint32_t addr) {
    asm volatile("ldmatrix.sync.aligned.m8n8.x2.shared.b16 {%0,%1}, [%2];"
                 : "=r"(r0), "=r"(r1) : "r"(addr));
}
__device__ __forceinline__ void mma16816(float* c, uint32_t a0, uint32_t a1, uint32_t a2, uint32_t a3,
                                         uint32_t b0, uint32_t b1) {
    asm volatile("mma.sync.aligned.m16n8k16.row.col.f32.f16.f16.f32 "
                 "{%0,%1,%2,%3}, {%4,%5,%6,%7}, {%8,%9}, {%0,%1,%2,%3};"
                 : "+f"(c[0]), "+f"(c[1]), "+f"(c[2]), "+f"(c[3])
                 : "r"(a0), "r"(a1), "r"(a2), "r"(a3), "r"(b0), "r"(b1));
}

// Thh tile layout: tile = (k>>6), inside: elem = b*64 + (((k&63)>>3) ^ (b&7))*8 + (k&7)
__device__ __forceinline__ int thh_off(int k, int b) {
    int r = k & 63;
    return (k >> 6) * 1024 + b * 64 + ((((r >> 3) ^ (b & 7))) << 3) + (r & 7);
}

// ---------------- kernel 1: repack A -> scaled fp16 swizzled tiles ----------------
// tile (j, kt) covers rows [j*64, ..), cols [kt*64, ..); base = (j*NT+kt)*4096
// in-tile elem (r, c, e) stored at r*64 + ((c^(r&7))*8) + e
__global__ void __launch_bounds__(256) repack_kernel(const float* __restrict__ A) {
    size_t id = (size_t)blockIdx.x * 256 + threadIdx.x;   // one thread per 8 elems
    if (id >= (size_t)NT * NT * 512) return;
    int c  = (int)(id & 7);
    int r  = (int)((id >> 3) & 63);
    int kt = (int)((id >> 9) % NT);
    int j  = (int)(id / ((size_t)512 * NT));
    int row  = j * 64 + r;
    int colb = kt * 64 + c * 8;
    float v[8];
#pragma unroll
    for (int e = 0; e < 8; e++) {
        int col = colb + e;
        float x = 0.f;
        if (row < L_TOT && col < L_TOT) {
            x = A[(size_t)row * L_TOT + col];
            if (row == col) x -= 1.0f;
        }
        v[e] = x * SCALE;
    }
    size_t base = ((size_t)j * NT + kt) * 4096 + r * 64 + ((c ^ (r & 7)) * 8);
    __half2* p = reinterpret_cast<__half2*>(d_Er + base);
    p[0] = __floats2half2_rn(v[0], v[1]);
    p[1] = __floats2half2_rn(v[2], v[3]);
    p[2] = __floats2half2_rn(v[4], v[5]);
    p[3] = __floats2half2_rn(v[6], v[7]);
}

// ---------------- kernel 2: init state + b vector ----------------
__global__ void __launch_bounds__(256) init_kernel(const float* __restrict__ Bm,
                                                   const float* __restrict__ theta) {
    int idx = blockIdx.x * 256 + threadIdx.x;
    if (idx < LP * 16) {
        int k = idx >> 4, b = idx & 15;
        float v = (k < L_TOT) ? theta[k] : 0.f;
        d_Th[0][idx] = v;
        d_Thh[0][thh_off(k, b)] = __float2half(v);
        if (b == 0) d_bvec[k] = (k < L_TOT) ? Bm[k] : 0.f;
    }
}

// ---------------- kernel 3: one recurrence step (TMA-bulk pipelined) ----------------
// 146 CTAs x 288 threads: warps 0-7 consumers (wid>>2 = K-half, wid&3 = m-tile),
// warp 8 lane 0 = TMA producer.
__global__ void __launch_bounds__(288) step_kernel(const float* __restrict__ xs, int t, int parity) {
    extern __shared__ char smem[];
    const uint32_t smem_u = (uint32_t)__cvta_generic_to_shared(smem);
    float* sD = (float*)(smem + STAGES * STAGE_BYTES);                 // 64*17 floats
    const uint32_t mb_full  = smem_u + STAGES * STAGE_BYTES + 4352;    // full[s]  = +s*8
    const uint32_t mb_empty = mb_full + 64;                            // empty[s] = +s*8

    const int tid = threadIdx.x;
    const int wid = tid >> 5, lane = tid & 31;
    const int row0 = blockIdx.x * 64;

    const float*  __restrict__ Th_src  = d_Th[parity];
    float*        __restrict__ Th_dst  = d_Th[parity ^ 1];
    const __half* __restrict__ Thh_src = d_Thh[parity];
    __half*       __restrict__ Thh_dst = d_Thh[parity ^ 1];

    if (tid == 0) {
#pragma unroll
        for (int s = 0; s < STAGES; s++) {
            mbar_init(mb_full  + s * 8, 1);
            mbar_init(mb_empty + s * 8, 256);
        }
        asm volatile("fence.proxy.async.shared::cta;" ::: "memory");
    }
    __syncthreads();

    if (wid < 8) {
        // -------- consumer --------
        const int h  = wid >> 2;
        const int mt = wid & 3;
        const int ar = mt * 16 + (lane & 15);
        const int arx = ar & 7;
        const int ach = lane >> 4;
        const uint32_t aOff = (uint32_t)(ar * 64) * 2 + h * 8192u;
        const int bn = lane & 7;
        const int kc = (lane >> 3) & 1;
        const uint32_t bOff = 16384u + h * 2048u + (uint32_t)bn * 128;

        float acc[2][4];
#pragma unroll
        for (int n = 0; n < 2; n++)
#pragma unroll
            for (int k = 0; k < 4; k++) acc[n][k] = 0.f;

        int phase = 0;
        for (int i = 0; i < NI; i++) {
            const int s = i & (STAGES - 1);
            if (i && s == 0) phase ^= 1;
            mbar_wait(mb_full + s * 8, phase);

            const uint32_t stage = smem_u + s * STAGE_BYTES;
            const uint32_t aBase = stage + aOff;
            const uint32_t bBase = stage + bOff;
#pragma unroll
            for (int kk = 0; kk < 4; kk++) {
                const int c  = kk * 2 + ach;
                const int cs = c ^ arx;
                uint32_t a0, a1, a2, a3;
                ldmatrix_x4(a0, a1, a2, a3, aBase + (uint32_t)(cs * 16));
                const int c2 = kk * 2 + kc;
                const uint32_t bAddr0 = bBase + (uint32_t)((c2 ^ bn) * 16);
                uint32_t b00, b01, b10, b11;
                ldmatrix_x2(b00, b01, bAddr0);            // n 0-7
                ldmatrix_x2(b10, b11, bAddr0 + 1024);     // n 8-15
                mma16816(acc[0], a0, a1, a2, a3, b00, b01);
                mma16816(acc[1], a0, a1, a2, a3, b10, b11);
            }
            mbar_arrive(mb_empty + s * 8);
        }

        // stash accumulators to sD (two K-halves reduced below)
        const int dr = mt * 16 + (lane >> 2);
        const int dc = (lane & 3) * 2;
        __syncthreads();   // paired with sync below; warp 8 participates
        if (h == 0) {
#pragma unroll
            for (int n = 0; n < 2; n++) {
                sD[dr * 17 + n * 8 + dc]           = acc[n][0];
                sD[dr * 17 + n * 8 + dc + 1]       = acc[n][1];
                sD[(dr + 8) * 17 + n * 8 + dc]     = acc[n][2];
                sD[(dr + 8) * 17 + n * 8 + dc + 1] = acc[n][3];
            }
        }
        __syncthreads();
        if (h == 1) {
#pragma unroll
            for (int n = 0; n < 2; n++) {
                sD[dr * 17 + n * 8 + dc]           += acc[n][0];
                sD[dr * 17 + n * 8 + dc + 1]       += acc[n][1];
                sD[(dr + 8) * 17 + n * 8 + dc]     += acc[n][2];
                sD[(dr + 8) * 17 + n * 8 + dc + 1] += acc[n][3];
            }
        }
        __syncthreads();
    } else {
        // -------- producer (warp 8) --------
        if (lane == 0) {
            const __half* tA = d_Er + (size_t)blockIdx.x * NT * 4096;
#pragma unroll
            for (int s = 0; s < STAGES; s++) {
                const uint32_t fb = mb_full + s * 8;
                const uint32_t dst = smem_u + s * STAGE_BYTES;
                mbar_expect_tx(fb, STAGE_BYTES);
                bulk_ld(dst,          tA + (size_t)s * 4096,        8192, fb);
                bulk_ld(dst + 8192,   tA + (size_t)(73 + s) * 4096, 8192, fb);
                bulk_ld(dst + 16384,  Thh_src + (size_t)s * 1024,        2048, fb);
                bulk_ld(dst + 18432,  Thh_src + (size_t)(73 + s) * 1024, 2048, fb);
            }
            int ph = 0;
            for (int i = 0; i + STAGES < NI; i++) {
                const int s = i & (STAGES - 1);
                if (i && s == 0) ph ^= 1;
                mbar_wait(mb_empty + s * 8, ph);
                const int li = i + STAGES;
                const uint32_t fb = mb_full + s * 8;
                const uint32_t dst = smem_u + s * STAGE_BYTES;
                mbar_expect_tx(fb, STAGE_BYTES);
                bulk_ld(dst,          tA + (size_t)li * 4096,        8192, fb);
                bulk_ld(dst + 8192,   tA + (size_t)(73 + li) * 4096, 8192, fb);
                bulk_ld(dst + 16384,  Thh_src + (size_t)li * 1024,        2048, fb);
                bulk_ld(dst + 18432,  Thh_src + (size_t)(73 + li) * 1024, 2048, fb);
            }
        }
        __syncthreads();  // pair 1
        __syncthreads();  // pair 2
        __syncthreads();  // pair 3
    }

    // ---- state update: fp32 master + fp16 shadow (swizzled tile layout) ----
    if (tid < 256) {
#pragma unroll
        for (int e = 0; e < 4; e++) {
            int idx = tid + 256 * e;            // 64 rows * 16 batch
            int r = idx >> 4, b = idx & 15;
            int grow = row0 + r;
            float val = Th_src[grow * 16 + b]
                      + sD[r * 17 + b] * INV_SCALE
                      + d_bvec[grow] * xs[b * NSTEPS + t];
            Th_dst[grow * 16 + b] = val;
            Thh_dst[blockIdx.x * 1024 + b * 64 + ((((r >> 3) ^ (b & 7))) << 3) + (r & 7)]
                = __float2half(val);
        }
    }
}

// ---------------- kernel 4: MLP epilogue (unchanged, passing) ----------------
__global__ void __launch_bounds__(256) mlp_kernel(float* __restrict__ out) {
    __shared__ float sW1r[64], sb1r[64], sW2r[64 * 64], sb2r[64], sW3r[64], sb3r[1];
    __shared__ float sW1c[64], sb1c[64], sW2c[64 * 64], sb2c[64], sW3c[64 * 10], sb3c[10];
    __shared__ float sh1[4][64];
    __shared__ float sred[4][2][10];

    const int b  = blockIdx.x;
    const int t0 = blockIdx.y * 16;
    const float* __restrict__ Th = d_Th[0];

    for (int k = threadIdx.x; k < L_TOT; k += 256) {
        float v = Th[k * 16 + b];
        if      (k < 64)   sW1r[k] = v;
        else if (k < 128)  sb1r[k - 64] = v;
        else if (k < 4224) { int o = (k - 128) >> 6, in = (k - 128) & 63; sW2r[in * 64 + o] = v; }
        else if (k < 4288) sb2r[k - 4224] = v;
        else if (k < 4352) sW3r[k - 4288] = v;
        else if (k < 4353) sb3r[0] = v;
        else if (k < 4417) sW1c[k - 4353] = v;
        else if (k < 4481) sb1c[k - 4417] = v;
        else if (k < 8577) { int o = (k - 4481) >> 6, in = (k - 4481) & 63; sW2c[in * 64 + o] = v; }
        else if (k < 8641) sb2c[k - 8577] = v;
        else if (k < 9281) { int o = (k - 8641) >> 6, in = (k - 8641) & 63; sW3c[in * 10 + o] = v; }
        else               sb3c[k - 9281] = v;
    }
    __syncthreads();

    const int g = threadIdx.x >> 6, i = threadIdx.x & 63;
    const int wing = (threadIdx.x >> 5) & 1, lane = threadIdx.x & 31;

    for (int tl = 0; tl < 4; tl++) {
        const int t = t0 + tl * 4 + g;
        const float ts = (float)t * (1.0f / 255.0f);

        float h1 = fmaxf(fmaf(sW1r[i], ts, sb1r[i]), 0.f);
        sh1[g][i] = h1;
        __syncthreads();
        float a2 = sb2r[i];
#pragma unroll
        for (int j = 0; j < 64; j++) a2 = fmaf(sW2r[j * 64 + i], sh1[g][j], a2);
        float h2 = fmaxf(a2, 0.f);
        float v = sW3r[i] * h2;
#pragma unroll
        for (int off = 16; off > 0; off >>= 1) v += __shfl_down_sync(0xffffffffu, v, off);
        if (lane == 0) sred[g][wing][0] = v;
        __syncthreads();
        if (i == 0) out[b * 256 + t] = sred[g][0][0] + sred[g][1][0] + sb3r[0];
        __syncthreads();

        float h1c = fmaxf(fmaf(sW1c[i], ts, sb1c[i]), 0.f);
        sh1[g][i] = h1c;
        __syncthreads();
        float a2c = sb2c[i];
#pragma unroll
        for (int j = 0; j < 64; j++) a2c = fmaf(sW2c[j * 64 + i], sh1[g][j], a2c);
        float h2c = fmaxf(a2c, 0.f);
        float vo[10];
#pragma unroll
        for (int o = 0; o < 10; o++) vo[o] = sW3c[i * 10 + o] * h2c;
#pragma unroll
        for (int off = 16; off > 0; off >>= 1)
#pragma unroll
            for (int o = 0; o < 10; o++) vo[o] += __shfl_down_sync(0xffffffffu, vo[o], off);
        if (lane == 0)
#pragma unroll
            for (int o = 0; o < 10; o++) sred[g][wing][o] = vo[o];
        __syncthreads();
        if (i < 10) out[4096 + (b * 256 + t) * 10 + i] = sred[g][0][i] + sred[g][1][i] + sb3c[i];
        __syncthreads();
    }
}

// ---------------- host launch ----------------
extern "C" void kernel_launch(void* const* d_in, const int* in_sizes, int n_in,
                              void* d_out, int out_size) {
    const float* xs    = (const float*)d_in[0];
    const float* A     = (const float*)d_in[1];
    const float* Bm    = (const float*)d_in[2];
    const float* theta = (const float*)d_in[3];
    float* out = (float*)d_out;

    constexpr int SMEM_BYTES = STAGES * STAGE_BYTES + 64 * 17 * 4 + 128;  // 168320
    cudaFuncSetAttribute(step_kernel, cudaFuncAttributeMaxDynamicSharedMemorySize, SMEM_BYTES);

    repack_kernel<<<2 * NT * NT, 256>>>(A);
    init_kernel<<<(LP * 16 + 255) / 256, 256>>>(Bm, theta);
    for (int t = 0; t < NSTEPS; t++)
        step_kernel<<<NT, 288, SMEM_BYTES>>>(xs, t, t & 1);
    mlp_kernel<<<dim3(16, 16), 256>>>(out);
}

// round 3
// speedup vs baseline: 1.5332x; 1.2434x over previous
#include <cuda_runtime.h>
#include <cuda_fp16.h>
#include <cstdint>

// ---------------- problem constants ----------------
#define L_TOT  9291
#define LP     9344          // 146*64
#define NT     146           // 64-wide tiles per dimension
#define NI     73            // k-iterations per K-half
#define NSTEPS 256
#define STAGES 8
#define STAGE_BYTES 20480    // 2x8KB A + 2x2KB B
#define SCALE      16384.0f
#define INV_SCALE  (1.0f/16384.0f)

// ---------------- device scratch ----------------
__device__ __align__(16) __half d_Er[(size_t)NT * NT * 4096];  // repacked scaled (A-I), fp16, swizzled tiles
__device__ __align__(16) float  d_Th[2][LP * 16];              // fp32 master state, ping-pong
__device__ __align__(16) __half d_Thh[2][NT * 1024];           // fp16 shadow state, swizzled [n][k] tiles
__device__ __align__(16) float  d_bvec[LP];

// ---------------- PTX helpers ----------------
__device__ __forceinline__ void mbar_init(uint32_t a, uint32_t cnt) {
    asm volatile("mbarrier.init.shared.b64 [%0], %1;" :: "r"(a), "r"(cnt) : "memory");
}
__device__ __forceinline__ void mbar_arrive(uint32_t a) {
    asm volatile("mbarrier.arrive.shared.b64 _, [%0];" :: "r"(a) : "memory");
}
__device__ __forceinline__ void mbar_expect_tx(uint32_t a, uint32_t bytes) {
    asm volatile("mbarrier.arrive.expect_tx.shared.b64 _, [%0], %1;" :: "r"(a), "r"(bytes) : "memory");
}
__device__ __forceinline__ void mbar_wait(uint32_t a, uint32_t parity) {
    asm volatile(
        "{\n\t.reg .pred P;\n"
        "W%=:\n\tmbarrier.try_wait.parity.acquire.cta.shared::cta.b64 P, [%0], %1, 0x989680;\n"
        "\t@P bra D%=;\n\tbra W%=;\nD%=:\n\t}"
        :: "r"(a), "r"(parity) : "memory");
}
__device__ __forceinline__ void bulk_ld(uint32_t dst, const void* src, uint32_t bytes, uint32_t mb) {
    asm volatile("cp.async.bulk.shared::cluster.global.mbarrier::complete_tx::bytes [%0], [%1], %2, [%3];"
                 :: "r"(dst), "l"(src), "r"(bytes), "r"(mb) : "memory");
}
__device__ __forceinline__ void ldmatrix_x4(uint32_t& r0, uint32_t& r1, uint32_t& r2, uint32_t& r3, uint32_t addr) {
    asm volatile("ldmatrix.sync.aligned.m8n8.x4.shared.b16 {%0,%1,%2,%3}, [%4];"
                 : "=r"(r0), "=r"(r1), "=r"(r2), "=r"(r3) : "r"(addr));
}
__device__ __forceinline__ void ldmatrix_x2(uint32_t& r0, uint32_t& r1, uint32_t addr) {
    asm volatile("ldmatrix.sync.aligned.m8n8.x2.shared.b16 {%0,%1}, [%2];"
                 : "=r"(r0), "=r"(r1) : "r"(addr));
}
__device__ __forceinline__ void mma16816(float* c, uint32_t a0, uint32_t a1, uint32_t a2, uint32_t a3,
                                         uint32_t b0, uint32_t b1) {
    asm volatile("mma.sync.aligned.m16n8k16.row.col.f32.f16.f16.f32 "
                 "{%0,%1,%2,%3}, {%4,%5,%6,%7}, {%8,%9}, {%0,%1,%2,%3};"
                 : "+f"(c[0]), "+f"(c[1]), "+f"(c[2]), "+f"(c[3])
                 : "r"(a0), "r"(a1), "r"(a2), "r"(a3), "r"(b0), "r"(b1));
}

// Thh tile layout: tile = (k>>6), inside: elem = b*64 + (((k&63)>>3) ^ (b&7))*8 + (k&7)
__device__ __forceinline__ int thh_off(int k, int b) {
    int r = k & 63;
    return (k >> 6) * 1024 + b * 64 + ((((r >> 3) ^ (b & 7))) << 3) + (r & 7);
}

// ---------------- kernel 1: repack A -> scaled fp16 swizzled tiles ----------------
__global__ void __launch_bounds__(256) repack_kernel(const float* __restrict__ A) {
    size_t id = (size_t)blockIdx.x * 256 + threadIdx.x;   // one thread per 8 elems
    if (id >= (size_t)NT * NT * 512) return;
    int c  = (int)(id & 7);
    int r  = (int)((id >> 3) & 63);
    int kt = (int)((id >> 9) % NT);
    int j  = (int)(id / ((size_t)512 * NT));
    int row  = j * 64 + r;
    int colb = kt * 64 + c * 8;
    float v[8];
#pragma unroll
    for (int e = 0; e < 8; e++) {
        int col = colb + e;
        float x = 0.f;
        if (row < L_TOT && col < L_TOT) {
            x = A[(size_t)row * L_TOT + col];
            if (row == col) x -= 1.0f;
        }
        v[e] = x * SCALE;
    }
    size_t base = ((size_t)j * NT + kt) * 4096 + r * 64 + ((c ^ (r & 7)) * 8);
    __half2* p = reinterpret_cast<__half2*>(d_Er + base);
    p[0] = __floats2half2_rn(v[0], v[1]);
    p[1] = __floats2half2_rn(v[2], v[3]);
    p[2] = __floats2half2_rn(v[4], v[5]);
    p[3] = __floats2half2_rn(v[6], v[7]);
}

// ---------------- kernel 2: init state + b vector ----------------
__global__ void __launch_bounds__(256) init_kernel(const float* __restrict__ Bm,
                                                   const float* __restrict__ theta) {
    int idx = blockIdx.x * 256 + threadIdx.x;
    if (idx < LP * 16) {
        int k = idx >> 4, b = idx & 15;
        float v = (k < L_TOT) ? theta[k] : 0.f;
        d_Th[0][idx] = v;
        d_Thh[0][thh_off(k, b)] = __float2half(v);
        if (b == 0) d_bvec[k] = (k < L_TOT) ? Bm[k] : 0.f;
    }
}

// ---------------- kernel 3: one recurrence step (TMA pipelined, alternating k-direction) ----------------
// 146 CTAs x 288 threads: warps 0-7 consumers (wid>>2 = K-half, wid&3 = m-tile),
// warp 8 lane 0 = TMA producer. dir flips each step so step t+1 re-reads what
// step t left resident in L2 (E is 172MB vs 126MB L2 -> ~70% hit with reversal).
__global__ void __launch_bounds__(288) step_kernel(const float* __restrict__ xs, int t, int parity, int dir) {
    extern __shared__ char smem[];
    const uint32_t smem_u = (uint32_t)__cvta_generic_to_shared(smem);
    float* sD = (float*)(smem + STAGES * STAGE_BYTES);                 // 64*17 floats
    const uint32_t mb_full  = smem_u + STAGES * STAGE_BYTES + 4352;    // full[s]  = +s*8
    const uint32_t mb_empty = mb_full + 64;                            // empty[s] = +s*8

    const int tid = threadIdx.x;
    const int wid = tid >> 5, lane = tid & 31;
    const int row0 = blockIdx.x * 64;

    const float*  __restrict__ Th_src  = d_Th[parity];
    float*        __restrict__ Th_dst  = d_Th[parity ^ 1];
    const __half* __restrict__ Thh_src = d_Thh[parity];
    __half*       __restrict__ Thh_dst = d_Thh[parity ^ 1];

    if (tid == 0) {
#pragma unroll
        for (int s = 0; s < STAGES; s++) {
            mbar_init(mb_full  + s * 8, 1);
            mbar_init(mb_empty + s * 8, 8);      // one arrive per consumer warp
        }
        asm volatile("fence.proxy.async.shared::cta;" ::: "memory");
    }
    __syncthreads();

    if (wid < 8) {
        // -------- consumer --------
        const int h  = wid >> 2;
        const int mt = wid & 3;
        const int ar = mt * 16 + (lane & 15);
        const int arx = ar & 7;
        const int ach = lane >> 4;
        const uint32_t aOff = (uint32_t)(ar * 64) * 2 + h * 8192u;
        const int bn = lane & 7;
        const int kc = (lane >> 3) & 1;
        const uint32_t bOff = 16384u + h * 2048u + (uint32_t)bn * 128;

        float acc[2][4];
#pragma unroll
        for (int n = 0; n < 2; n++)
#pragma unroll
            for (int k = 0; k < 4; k++) acc[n][k] = 0.f;

        int phase = 0;
        for (int i = 0; i < NI; i++) {
            const int s = i & (STAGES - 1);
            if (i && s == 0) phase ^= 1;
            mbar_wait(mb_full + s * 8, phase);

            const uint32_t stage = smem_u + s * STAGE_BYTES;
            const uint32_t aBase = stage + aOff;
            const uint32_t bBase = stage + bOff;
#pragma unroll
            for (int kk = 0; kk < 4; kk++) {
                const int c  = kk * 2 + ach;
                const int cs = c ^ arx;
                uint32_t a0, a1, a2, a3;
                ldmatrix_x4(a0, a1, a2, a3, aBase + (uint32_t)(cs * 16));
                const int c2 = kk * 2 + kc;
                const uint32_t bAddr0 = bBase + (uint32_t)((c2 ^ bn) * 16);
                uint32_t b00, b01, b10, b11;
                ldmatrix_x2(b00, b01, bAddr0);            // n 0-7
                ldmatrix_x2(b10, b11, bAddr0 + 1024);     // n 8-15
                mma16816(acc[0], a0, a1, a2, a3, b00, b01);
                mma16816(acc[1], a0, a1, a2, a3, b10, b11);
            }
            if (lane == 0) mbar_arrive(mb_empty + s * 8);
        }

        // reduce the two K-halves through shared memory
        const int dr = mt * 16 + (lane >> 2);
        const int dc = (lane & 3) * 2;
        __syncthreads();   // pair 1 (warp 8 participates)
        if (h == 0) {
#pragma unroll
            for (int n = 0; n < 2; n++) {
                sD[dr * 17 + n * 8 + dc]           = acc[n][0];
                sD[dr * 17 + n * 8 + dc + 1]       = acc[n][1];
                sD[(dr + 8) * 17 + n * 8 + dc]     = acc[n][2];
                sD[(dr + 8) * 17 + n * 8 + dc + 1] = acc[n][3];
            }
        }
        __syncthreads();   // pair 2
        if (h == 1) {
#pragma unroll
            for (int n = 0; n < 2; n++) {
                sD[dr * 17 + n * 8 + dc]           += acc[n][0];
                sD[dr * 17 + n * 8 + dc + 1]       += acc[n][1];
                sD[(dr + 8) * 17 + n * 8 + dc]     += acc[n][2];
                sD[(dr + 8) * 17 + n * 8 + dc + 1] += acc[n][3];
            }
        }
        __syncthreads();   // pair 3
    } else {
        // -------- producer (warp 8) --------
        if (lane == 0) {
            const __half* tA = d_Er + (size_t)blockIdx.x * NT * 4096;
#pragma unroll
            for (int s = 0; s < STAGES; s++) {
                const int ki = dir ? (NI - 1 - s) : s;
                const uint32_t fb = mb_full + s * 8;
                const uint32_t dst = smem_u + s * STAGE_BYTES;
                mbar_expect_tx(fb, STAGE_BYTES);
                bulk_ld(dst,          tA + (size_t)ki * 4096,        8192, fb);
                bulk_ld(dst + 8192,   tA + (size_t)(73 + ki) * 4096, 8192, fb);
                bulk_ld(dst + 16384,  Thh_src + (size_t)ki * 1024,        2048, fb);
                bulk_ld(dst + 18432,  Thh_src + (size_t)(73 + ki) * 1024, 2048, fb);
            }
            int ph = 0;
            for (int i = 0; i + STAGES < NI; i++) {
                const int s = i & (STAGES - 1);
                if (i && s == 0) ph ^= 1;
                mbar_wait(mb_empty + s * 8, ph);
                const int li = i + STAGES;
                const int ki = dir ? (NI - 1 - li) : li;
                const uint32_t fb = mb_full + s * 8;
                const uint32_t dst = smem_u + s * STAGE_BYTES;
                mbar_expect_tx(fb, STAGE_BYTES);
                bulk_ld(dst,          tA + (size_t)ki * 4096,        8192, fb);
                bulk_ld(dst + 8192,   tA + (size_t)(73 + ki) * 4096, 8192, fb);
                bulk_ld(dst + 16384,  Thh_src + (size_t)ki * 1024,        2048, fb);
                bulk_ld(dst + 18432,  Thh_src + (size_t)(73 + ki) * 1024, 2048, fb);
            }
        }
        __syncthreads();  // pair 1
        __syncthreads();  // pair 2
        __syncthreads();  // pair 3
    }

    // ---- state update: fp32 master + fp16 shadow (swizzled tile layout) ----
    if (tid < 256) {
#pragma unroll
        for (int e = 0; e < 4; e++) {
            int idx = tid + 256 * e;            // 64 rows * 16 batch
            int r = idx >> 4, b = idx & 15;
            int grow = row0 + r;
            float val = Th_src[grow * 16 + b]
                      + sD[r * 17 + b] * INV_SCALE
                      + d_bvec[grow] * xs[b * NSTEPS + t];
            Th_dst[grow * 16 + b] = val;
            Thh_dst[blockIdx.x * 1024 + b * 64 + ((((r >> 3) ^ (b & 7))) << 3) + (r & 7)]
                = __float2half(val);
        }
    }
}

// ---------------- kernel 4: MLP epilogue ----------------
__global__ void __launch_bounds__(256) mlp_kernel(float* __restrict__ out) {
    __shared__ float sW1r[64], sb1r[64], sW2r[64 * 64], sb2r[64], sW3r[64], sb3r[1];
    __shared__ float sW1c[64], sb1c[64], sW2c[64 * 64], sb2c[64], sW3c[64 * 10], sb3c[10];
    __shared__ float sh1[4][64];
    __shared__ float sred[4][2][10];

    const int b  = blockIdx.x;
    const int t0 = blockIdx.y * 16;
    const float* __restrict__ Th = d_Th[0];

    for (int k = threadIdx.x; k < L_TOT; k += 256) {
        float v = Th[k * 16 + b];
        if      (k < 64)   sW1r[k] = v;
        else if (k < 128)  sb1r[k - 64] = v;
        else if (k < 4224) { int o = (k - 128) >> 6, in = (k - 128) & 63; sW2r[in * 64 + o] = v; }
        else if (k < 4288) sb2r[k - 4224] = v;
        else if (k < 4352) sW3r[k - 4288] = v;
        else if (k < 4353) sb3r[0] = v;
        else if (k < 4417) sW1c[k - 4353] = v;
        else if (k < 4481) sb1c[k - 4417] = v;
        else if (k < 8577) { int o = (k - 4481) >> 6, in = (k - 4481) & 63; sW2c[in * 64 + o] = v; }
        else if (k < 8641) sb2c[k - 8577] = v;
        else if (k < 9281) { int o = (k - 8641) >> 6, in = (k - 8641) & 63; sW3c[in * 10 + o] = v; }
        else               sb3c[k - 9281] = v;
    }
    __syncthreads();

    const int g = threadIdx.x >> 6, i = threadIdx.x & 63;
    const int wing = (threadIdx.x >> 5) & 1, lane = threadIdx.x & 31;

    for (int tl = 0; tl < 4; tl++) {
        const int t = t0 + tl * 4 + g;
        const float ts = (float)t * (1.0f / 255.0f);

        float h1 = fmaxf(fmaf(sW1r[i], ts, sb1r[i]), 0.f);
        sh1[g][i] = h1;
        __syncthreads();
        float a2 = sb2r[i];
#pragma unroll
        for (int j = 0; j < 64; j++) a2 = fmaf(sW2r[j * 64 + i], sh1[g][j], a2);
        float h2 = fmaxf(a2, 0.f);
        float v = sW3r[i] * h2;
#pragma unroll
        for (int off = 16; off > 0; off >>= 1) v += __shfl_down_sync(0xffffffffu, v, off);
        if (lane == 0) sred[g][wing][0] = v;
        __syncthreads();
        if (i == 0) out[b * 256 + t] = sred[g][0][0] + sred[g][1][0] + sb3r[0];
        __syncthreads();

        float h1c = fmaxf(fmaf(sW1c[i], ts, sb1c[i]), 0.f);
        sh1[g][i] = h1c;
        __syncthreads();
        float a2c = sb2c[i];
#pragma unroll
        for (int j = 0; j < 64; j++) a2c = fmaf(sW2c[j * 64 + i], sh1[g][j], a2c);
        float h2c = fmaxf(a2c, 0.f);
        float vo[10];
#pragma unroll
        for (int o = 0; o < 10; o++) vo[o] = sW3c[i * 10 + o] * h2c;
#pragma unroll
        for (int off = 16; off > 0; off >>= 1)
#pragma unroll
            for (int o = 0; o < 10; o++) vo[o] += __shfl_down_sync(0xffffffffu, vo[o], off);
        if (lane == 0)
#pragma unroll
            for (int o = 0; o < 10; o++) sred[g][wing][o] = vo[o];
        __syncthreads();
        if (i < 10) out[4096 + (b * 256 + t) * 10 + i] = sred[g][0][i] + sred[g][1][i] + sb3c[i];
        __syncthreads();
    }
}

// ---------------- host launch ----------------
extern "C" void kernel_launch(void* const* d_in, const int* in_sizes, int n_in,
                              void* d_out, int out_size) {
    const float* xs    = (const float*)d_in[0];
    const float* A     = (const float*)d_in[1];
    const float* Bm    = (const float*)d_in[2];
    const float* theta = (const float*)d_in[3];
    float* out = (float*)d_out;

    constexpr int SMEM_BYTES = STAGES * STAGE_BYTES + 64 * 17 * 4 + 128;  // 168320
    cudaFuncSetAttribute(step_kernel, cudaFuncAttributeMaxDynamicSharedMemorySize, SMEM_BYTES);

    repack_kernel<<<2 * NT * NT, 256>>>(A);
    init_kernel<<<(LP * 16 + 255) / 256, 256>>>(Bm, theta);
    for (int t = 0; t < NSTEPS; t++)
        step_kernel<<<NT, 288, SMEM_BYTES>>>(xs, t, t & 1, t & 1);
    mlp_kernel<<<dim3(16, 16), 256>>>(out);
}

// round 4
// speedup vs baseline: 1.5856x; 1.0342x over previous
#include <cuda_runtime.h>
#include <cuda_fp16.h>
#include <cstdint>

// ---------------- problem constants ----------------
#define L_TOT  9291
#define LP     9344          // 146*64
#define NT     146           // 64-wide tiles per dimension
#define NI     73            // k-iterations per K-half
#define NSTEPS 256
#define STAGES 10
#define STAGE_BYTES 20480    // 2x8KB A + 2x2KB B
#define SCALE      16384.0f
#define INV_SCALE  (1.0f/16384.0f)

// ---------------- device scratch ----------------
__device__ __align__(16) __half d_Er[(size_t)NT * NT * 4096];  // repacked scaled (A-I), fp16, swizzled tiles
__device__ __align__(16) float  d_Th[LP * 16];                 // fp32 master state (init + final only)
__device__ __align__(16) __half d_Thh[2][NT * 1024];           // fp16 shadow state, swizzled tiles, ping-pong
__device__ __align__(16) float  d_bvec[LP];
__device__ unsigned int g_bar;                                 // grid barrier counter

// ---------------- PTX helpers ----------------
__device__ __forceinline__ void mbar_init(uint32_t a, uint32_t cnt) {
    asm volatile("mbarrier.init.shared.b64 [%0], %1;" :: "r"(a), "r"(cnt) : "memory");
}
__device__ __forceinline__ void mbar_arrive(uint32_t a) {
    asm volatile("mbarrier.arrive.shared.b64 _, [%0];" :: "r"(a) : "memory");
}
__device__ __forceinline__ void mbar_expect_tx(uint32_t a, uint32_t bytes) {
    asm volatile("mbarrier.arrive.expect_tx.shared.b64 _, [%0], %1;" :: "r"(a), "r"(bytes) : "memory");
}
__device__ __forceinline__ void mbar_wait(uint32_t a, uint32_t parity) {
    asm volatile(
        "{\n\t.reg .pred P;\n"
        "W%=:\n\tmbarrier.try_wait.parity.acquire.cta.shared::cta.b64 P, [%0], %1, 0x989680;\n"
        "\t@P bra D%=;\n\tbra W%=;\nD%=:\n\t}"
        :: "r"(a), "r"(parity) : "memory");
}
__device__ __forceinline__ void bulk_ld(uint32_t dst, const void* src, uint32_t bytes, uint32_t mb) {
    asm volatile("cp.async.bulk.shared::cluster.global.mbarrier::complete_tx::bytes [%0], [%1], %2, [%3];"
                 :: "r"(dst), "l"(src), "r"(bytes), "r"(mb) : "memory");
}
__device__ __forceinline__ void ldmatrix_x4(uint32_t& r0, uint32_t& r1, uint32_t& r2, uint32_t& r3, uint32_t addr) {
    asm volatile("ldmatrix.sync.aligned.m8n8.x4.shared.b16 {%0,%1,%2,%3}, [%4];"
                 : "=r"(r0), "=r"(r1), "=r"(r2), "=r"(r3) : "r"(addr));
}
__device__ __forceinline__ void ldmatrix_x2(uint32_t& r0, uint32_t& r1, uint32_t addr) {
    asm volatile("ldmatrix.sync.aligned.m8n8.x2.shared.b16 {%0,%1}, [%2];"
                 : "=r"(r0), "=r"(r1) : "r"(addr));
}
__device__ __forceinline__ void mma16816(float* c, uint32_t a0, uint32_t a1, uint32_t a2, uint32_t a3,
                                         uint32_t b0, uint32_t b1) {
    asm volatile("mma.sync.aligned.m16n8k16.row.col.f32.f16.f16.f32 "
                 "{%0,%1,%2,%3}, {%4,%5,%6,%7}, {%8,%9}, {%0,%1,%2,%3};"
                 : "+f"(c[0]), "+f"(c[1]), "+f"(c[2]), "+f"(c[3])
                 : "r"(a0), "r"(a1), "r"(a2), "r"(a3), "r"(b0), "r"(b1));
}

// Thh tile layout: tile = (k>>6), inside: elem = b*64 + (((k&63)>>3) ^ (b&7))*8 + (k&7)
__device__ __forceinline__ int thh_off(int k, int b) {
    int r = k & 63;
    return (k >> 6) * 1024 + b * 64 + ((((r >> 3) ^ (b & 7))) << 3) + (r & 7);
}

// ---------------- kernel 1: repack A -> scaled fp16 swizzled tiles ----------------
__global__ void __launch_bounds__(256) repack_kernel(const float* __restrict__ A) {
    size_t id = (size_t)blockIdx.x * 256 + threadIdx.x;   // one thread per 8 elems
    if (id >= (size_t)NT * NT * 512) return;
    int c  = (int)(id & 7);
    int r  = (int)((id >> 3) & 63);
    int kt = (int)((id >> 9) % NT);
    int j  = (int)(id / ((size_t)512 * NT));
    int row  = j * 64 + r;
    int colb = kt * 64 + c * 8;
    float v[8];
#pragma unroll
    for (int e = 0; e < 8; e++) {
        int col = colb + e;
        float x = 0.f;
        if (row < L_TOT && col < L_TOT) {
            x = A[(size_t)row * L_TOT + col];
            if (row == col) x -= 1.0f;
        }
        v[e] = x * SCALE;
    }
    size_t base = ((size_t)j * NT + kt) * 4096 + r * 64 + ((c ^ (r & 7)) * 8);
    __half2* p = reinterpret_cast<__half2*>(d_Er + base);
    p[0] = __floats2half2_rn(v[0], v[1]);
    p[1] = __floats2half2_rn(v[2], v[3]);
    p[2] = __floats2half2_rn(v[4], v[5]);
    p[3] = __floats2half2_rn(v[6], v[7]);
}

// ---------------- kernel 2: init state + b vector + grid barrier reset ----------------
__global__ void __launch_bounds__(256) init_kernel(const float* __restrict__ Bm,
                                                   const float* __restrict__ theta) {
    if (blockIdx.x == 0 && threadIdx.x == 0) g_bar = 0u;
    int idx = blockIdx.x * 256 + threadIdx.x;
    if (idx < LP * 16) {
        int k = idx >> 4, b = idx & 15;
        float v = (k < L_TOT) ? theta[k] : 0.f;
        d_Th[idx] = v;
        d_Thh[0][thh_off(k, b)] = __float2half(v);
        if (b == 0) d_bvec[k] = (k < L_TOT) ? Bm[k] : 0.f;
    }
}

// ---------------- kernel 3: persistent recurrence (all 256 steps, one launch) ----------------
// 146 CTAs (one wave) x 288 threads. Warps 0-7 consumers, warp 8 lane 0 = TMA producer.
// Pipeline stage/phase counters continue across steps (global iteration index).
// k-direction alternates per step for cross-step L2 reuse. Grid barrier between steps.
__global__ void __launch_bounds__(288) persist_kernel(const float* __restrict__ xs) {
    extern __shared__ char smem[];
    const uint32_t smem_u = (uint32_t)__cvta_generic_to_shared(smem);
    float* sD = (float*)(smem + STAGES * STAGE_BYTES);              // 64*17 floats
    const uint32_t mb_full  = smem_u + STAGES * STAGE_BYTES + 4352; // full[s]  = +s*8
    const uint32_t mb_empty = mb_full + 8 * STAGES;                 // empty[s] = +s*8

    const int tid = threadIdx.x;
    const int wid = tid >> 5, lane = tid & 31;
    const int row0 = blockIdx.x * 64;

    if (tid == 0) {
#pragma unroll
        for (int s = 0; s < STAGES; s++) {
            mbar_init(mb_full  + s * 8, 1);
            mbar_init(mb_empty + s * 8, 8);   // one arrive per consumer warp
        }
        asm volatile("fence.proxy.async.shared::cta;" ::: "memory");
    }
    __syncthreads();

    // ---- consumer constants ----
    const int h  = wid >> 2;
    const int mt = wid & 3;
    const int ar  = mt * 16 + (lane & 15);
    const int arx = ar & 7;
    const int ach = lane >> 4;
    const uint32_t aOff = (uint32_t)(ar * 64) * 2 + h * 8192u;
    const int bn = lane & 7;
    const int kc = (lane >> 3) & 1;
    const uint32_t bOff = 16384u + h * 2048u + (uint32_t)bn * 128;
    const int dr = mt * 16 + (lane >> 2);
    const int dc = (lane & 3) * 2;

    // ---- per-thread persistent state (fp32 master Theta in registers) ----
    const int bb = tid & 15;
    float myTh[4], myB[4];
    int rr[4], thhIdx[4];
    if (tid < 256) {
#pragma unroll
        for (int e = 0; e < 4; e++) {
            int idx = tid + 256 * e;            // 64 rows * 16 batch
            int r = idx >> 4;
            rr[e] = r;
            int grow = row0 + r;
            myTh[e] = d_Th[grow * 16 + bb];
            myB[e]  = d_bvec[grow];
            thhIdx[e] = blockIdx.x * 1024 + bb * 64 + ((((r >> 3) ^ (bb & 7))) << 3) + (r & 7);
        }
    }

    int cs = 0, cq = 0;            // consumer stage + phase (continue across steps)
    int ps = 0, pq = 0, pg = 0;    // producer stage + phase + global issue count

    for (int t = 0; t < NSTEPS; t++) {
        const int parity = t & 1;
        const int dir = t & 1;     // alternate k-direction for L2 reuse
        const __half* __restrict__ Thh_src = d_Thh[parity];
        __half*       __restrict__ Thh_dst = d_Thh[parity ^ 1];

        if (wid < 8) {
            // -------- consumer --------
            float acc[2][4];
#pragma unroll
            for (int n = 0; n < 2; n++)
#pragma unroll
                for (int k = 0; k < 4; k++) acc[n][k] = 0.f;

            for (int i = 0; i < NI; i++) {
                mbar_wait(mb_full + cs * 8, cq);
                const uint32_t stage = smem_u + cs * STAGE_BYTES;
                const uint32_t aBase = stage + aOff;
                const uint32_t bBase = stage + bOff;
#pragma unroll
                for (int kk = 0; kk < 4; kk++) {
                    const int c  = kk * 2 + ach;
                    const int cst = c ^ arx;
                    uint32_t a0, a1, a2, a3;
                    ldmatrix_x4(a0, a1, a2, a3, aBase + (uint32_t)(cst * 16));
                    const int c2 = kk * 2 + kc;
                    const uint32_t bAddr0 = bBase + (uint32_t)((c2 ^ bn) * 16);
                    uint32_t b00, b01, b10, b11;
                    ldmatrix_x2(b00, b01, bAddr0);            // n 0-7
                    ldmatrix_x2(b10, b11, bAddr0 + 1024);     // n 8-15
                    mma16816(acc[0], a0, a1, a2, a3, b00, b01);
                    mma16816(acc[1], a0, a1, a2, a3, b10, b11);
                }
                if (lane == 0) mbar_arrive(mb_empty + cs * 8);
                if (++cs == STAGES) { cs = 0; cq ^= 1; }
            }

            // reduce the two K-halves through shared memory
            __syncthreads();   // pair 1
            if (h == 0) {
#pragma unroll
                for (int n = 0; n < 2; n++) {
                    sD[dr * 17 + n * 8 + dc]           = acc[n][0];
                    sD[dr * 17 + n * 8 + dc + 1]       = acc[n][1];
                    sD[(dr + 8) * 17 + n * 8 + dc]     = acc[n][2];
                    sD[(dr + 8) * 17 + n * 8 + dc + 1] = acc[n][3];
                }
            }
            __syncthreads();   // pair 2
            if (h == 1) {
#pragma unroll
                for (int n = 0; n < 2; n++) {
                    sD[dr * 17 + n * 8 + dc]           += acc[n][0];
                    sD[dr * 17 + n * 8 + dc + 1]       += acc[n][1];
                    sD[(dr + 8) * 17 + n * 8 + dc]     += acc[n][2];
                    sD[(dr + 8) * 17 + n * 8 + dc + 1] += acc[n][3];
                }
            }
            __syncthreads();   // pair 3
        } else {
            // -------- producer (warp 8) --------
            if (lane == 0) {
                const __half* tA = d_Er + (size_t)blockIdx.x * NT * 4096;
                for (int i = 0; i < NI; i++) {
                    if (pg >= STAGES) mbar_wait(mb_empty + ps * 8, pq ^ 1);
                    const int ki = dir ? (NI - 1 - i) : i;
                    const uint32_t fb  = mb_full + ps * 8;
                    const uint32_t dst = smem_u + ps * STAGE_BYTES;
                    mbar_expect_tx(fb, STAGE_BYTES);
                    bulk_ld(dst,          tA + (size_t)ki * 4096,        8192, fb);
                    bulk_ld(dst + 8192,   tA + (size_t)(73 + ki) * 4096, 8192, fb);
                    bulk_ld(dst + 16384,  Thh_src + (size_t)ki * 1024,        2048, fb);
                    bulk_ld(dst + 18432,  Thh_src + (size_t)(73 + ki) * 1024, 2048, fb);
                    pg++;
                    if (++ps == STAGES) { ps = 0; pq ^= 1; }
                }
            }
            __syncthreads();  // pair 1
            __syncthreads();  // pair 2
            __syncthreads();  // pair 3
        }

        // ---- state update: registers + fp16 shadow write ----
        if (tid < 256) {
            const float xv = xs[bb * NSTEPS + t];
#pragma unroll
            for (int e = 0; e < 4; e++) {
                float val = myTh[e] + sD[rr[e] * 17 + bb] * INV_SCALE + myB[e] * xv;
                myTh[e] = val;
                Thh_dst[thhIdx[e]] = __float2half(val);
            }
            if (t == NSTEPS - 1) {
#pragma unroll
                for (int e = 0; e < 4; e++)
                    d_Th[(row0 + rr[e]) * 16 + bb] = myTh[e];
            }
        }

        // ---- grid barrier (all 146 CTAs resident: one wave) ----
        __threadfence();
        asm volatile("fence.proxy.async.global;" ::: "memory");
        __syncthreads();
        if (tid == 0) {
            atomicAdd(&g_bar, 1u);
            const unsigned target = (unsigned)NT * (unsigned)(t + 1);
            unsigned v;
            do {
                asm volatile("ld.global.acquire.gpu.u32 %0, [%1];" : "=r"(v) : "l"(&g_bar));
                if (v >= target) break;
                __nanosleep(32);
            } while (true);
        }
        __syncthreads();
    }
}

// ---------------- kernel 4: MLP epilogue ----------------
__global__ void __launch_bounds__(256) mlp_kernel(float* __restrict__ out) {
    __shared__ float sW1r[64], sb1r[64], sW2r[64 * 64], sb2r[64], sW3r[64], sb3r[1];
    __shared__ float sW1c[64], sb1c[64], sW2c[64 * 64], sb2c[64], sW3c[64 * 10], sb3c[10];
    __shared__ float sh1[4][64];
    __shared__ float sred[4][2][10];

    const int b  = blockIdx.x;
    const int t0 = blockIdx.y * 16;
    const float* __restrict__ Th = d_Th;

    for (int k = threadIdx.x; k < L_TOT; k += 256) {
        float v = Th[k * 16 + b];
        if      (k < 64)   sW1r[k] = v;
        else if (k < 128)  sb1r[k - 64] = v;
        else if (k < 4224) { int o = (k - 128) >> 6, in = (k - 128) & 63; sW2r[in * 64 + o] = v; }
        else if (k < 4288) sb2r[k - 4224] = v;
        else if (k < 4352) sW3r[k - 4288] = v;
        else if (k < 4353) sb3r[0] = v;
        else if (k < 4417) sW1c[k - 4353] = v;
        else if (k < 4481) sb1c[k - 4417] = v;
        else if (k < 8577) { int o = (k - 4481) >> 6, in = (k - 4481) & 63; sW2c[in * 64 + o] = v; }
        else if (k < 8641) sb2c[k - 8577] = v;
        else if (k < 9281) { int o = (k - 8641) >> 6, in = (k - 8641) & 63; sW3c[in * 10 + o] = v; }
        else               sb3c[k - 9281] = v;
    }
    __syncthreads();

    const int g = threadIdx.x >> 6, i = threadIdx.x & 63;
    const int wing = (threadIdx.x >> 5) & 1, lane = threadIdx.x & 31;

    for (int tl = 0; tl < 4; tl++) {
        const int t = t0 + tl * 4 + g;
        const float ts = (float)t * (1.0f / 255.0f);

        float h1 = fmaxf(fmaf(sW1r[i], ts, sb1r[i]), 0.f);
        sh1[g][i] = h1;
        __syncthreads();
        float a2 = sb2r[i];
#pragma unroll
        for (int j = 0; j < 64; j++) a2 = fmaf(sW2r[j * 64 + i], sh1[g][j], a2);
        float h2 = fmaxf(a2, 0.f);
        float v = sW3r[i] * h2;
#pragma unroll
        for (int off = 16; off > 0; off >>= 1) v += __shfl_down_sync(0xffffffffu, v, off);
        if (lane == 0) sred[g][wing][0] = v;
        __syncthreads();
        if (i == 0) out[b * 256 + t] = sred[g][0][0] + sred[g][1][0] + sb3r[0];
        __syncthreads();

        float h1c = fmaxf(fmaf(sW1c[i], ts, sb1c[i]), 0.f);
        sh1[g][i] = h1c;
        __syncthreads();
        float a2c = sb2c[i];
#pragma unroll
        for (int j = 0; j < 64; j++) a2c = fmaf(sW2c[j * 64 + i], sh1[g][j], a2c);
        float h2c = fmaxf(a2c, 0.f);
        float vo[10];
#pragma unroll
        for (int o = 0; o < 10; o++) vo[o] = sW3c[i * 10 + o] * h2c;
#pragma unroll
        for (int off = 16; off > 0; off >>= 1)
#pragma unroll
            for (int o = 0; o < 10; o++) vo[o] += __shfl_down_sync(0xffffffffu, vo[o], off);
        if (lane == 0)
#pragma unroll
            for (int o = 0; o < 10; o++) sred[g][wing][o] = vo[o];
        __syncthreads();
        if (i < 10) out[4096 + (b * 256 + t) * 10 + i] = sred[g][0][i] + sred[g][1][i] + sb3c[i];
        __syncthreads();
    }
}

// ---------------- host launch ----------------
extern "C" void kernel_launch(void* const* d_in, const int* in_sizes, int n_in,
                              void* d_out, int out_size) {
    const float* xs    = (const float*)d_in[0];
    const float* A     = (const float*)d_in[1];
    const float* Bm    = (const float*)d_in[2];
    const float* theta = (const float*)d_in[3];
    float* out = (float*)d_out;

    constexpr int SMEM_BYTES = STAGES * STAGE_BYTES + 64 * 17 * 4 + 16 * STAGES + 64;  // 209376
    cudaFuncSetAttribute(persist_kernel, cudaFuncAttributeMaxDynamicSharedMemorySize, SMEM_BYTES);

    repack_kernel<<<2 * NT * NT, 256>>>(A);
    init_kernel<<<(LP * 16 + 255) / 256, 256>>>(Bm, theta);
    persist_kernel<<<NT, 288, SMEM_BYTES>>>(xs);
    mlp_kernel<<<dim3(16, 16), 256>>>(out);
}